// round 12
// baseline (speedup 1.0000x reference)
#include <cuda_runtime.h>
#include <cuda_fp16.h>
#include <cuda_bf16.h>
#include <cstdint>

// ================= problem constants =================
constexpr int K_DIM = 1024;
constexpr int N_DIM = 4096;
constexpr int M_DIM = 32768;

constexpr int MT = 128;               // CTA tile M
constexpr int NT = 256;               // CTA tile N
constexpr int KT = 32;                // CTA tile K per stage
constexpr int STAGES = 5;
constexpr int NKT = K_DIM / KT;       // 32 k-iterations

constexpr int AROWB = 80;             // smem row stride: 64B data + 16B pad (conflict-free, 16B-aligned rows)
constexpr int A_STAGE_B = MT * AROWB; // 10240
constexpr int B_STAGE_B = NT * AROWB; // 20480
constexpr int STAGE_B = A_STAGE_B + B_STAGE_B;       // 30720
constexpr int SMEM_BIAS_B = 1024;
constexpr int SMEM_TOTAL = SMEM_BIAS_B + STAGES * STAGE_B;  // 154624

// ============ device scratch (__device__ globals; no allocs allowed) ============
__device__ __align__(128) __half g_xa[(size_t)M_DIM * K_DIM];  // BF15(x) as fp16, [M][K]
__device__ __align__(128) __half g_wh[(size_t)N_DIM * K_DIM];  // fp16(W), [N][K]

// ================= helpers =================
__device__ __forceinline__ uint32_t smem_u32(const void* p) {
    uint32_t a;
    asm("{ .reg .u64 t; cvta.to.shared.u64 t, %1; cvt.u32.u64 %0, t; }" : "=r"(a) : "l"(p));
    return a;
}
__device__ __forceinline__ void cp_async16(uint32_t s, const void* g) {
    asm volatile("cp.async.cg.shared.global [%0], [%1], 16;" :: "r"(s), "l"(g));
}
__device__ __forceinline__ void ldsm4(uint32_t* r, uint32_t addr) {
    asm volatile("ldmatrix.sync.aligned.m8n8.x4.shared.b16 {%0,%1,%2,%3}, [%4];"
                 : "=r"(r[0]), "=r"(r[1]), "=r"(r[2]), "=r"(r[3]) : "r"(addr));
}
__device__ __forceinline__ void mma16816(float* c, const uint32_t* a, uint32_t b0, uint32_t b1) {
    asm volatile(
        "mma.sync.aligned.m16n8k16.row.col.f32.f16.f16.f32 "
        "{%0,%1,%2,%3},{%4,%5,%6,%7},{%8,%9},{%0,%1,%2,%3};"
        : "+f"(c[0]), "+f"(c[1]), "+f"(c[2]), "+f"(c[3])
        : "r"(a[0]), "r"(a[1]), "r"(a[2]), "r"(a[3]), "r"(b0), "r"(b1));
}

// ================= conversion kernels (measured 77.5% HBM — done) =================
__global__ void conv_x_kernel(const float* __restrict__ x) {
    size_t i = ((size_t)blockIdx.x * blockDim.x + threadIdx.x) * 8;
    float4 f0 = *(const float4*)(x + i);
    float4 f1 = *(const float4*)(x + i + 4);
    auto bf15 = [](float v) { return __uint_as_float(__float_as_uint(v) & 0xFFFE0000u); };
    __half2 h[4];
    h[0] = __floats2half2_rn(bf15(f0.x), bf15(f0.y));
    h[1] = __floats2half2_rn(bf15(f0.z), bf15(f0.w));
    h[2] = __floats2half2_rn(bf15(f1.x), bf15(f1.y));
    h[3] = __floats2half2_rn(bf15(f1.z), bf15(f1.w));
    *(uint4*)(g_xa + i) = *(uint4*)h;
}

__global__ void conv_w_kernel(const float* __restrict__ w) {
    size_t i = ((size_t)blockIdx.x * blockDim.x + threadIdx.x) * 8;
    float4 f0 = *(const float4*)(w + i);
    float4 f1 = *(const float4*)(w + i + 4);
    __half2 h[4];
    h[0] = __floats2half2_rn(f0.x, f0.y);
    h[1] = __floats2half2_rn(f0.z, f0.w);
    h[2] = __floats2half2_rn(f1.x, f1.y);
    h[3] = __floats2half2_rn(f1.z, f1.w);
    *(uint4*)(g_wh + i) = *(uint4*)h;
}

// ================= GEMM kernel (raw mma.sync + ldmatrix, 5-stage cp.async) =================
// Fragment mapping verified: R5/R6 raw-mma output was bit-identical to R10 wmma output.
__global__ __launch_bounds__(256, 1)
void gemm_kernel(const float* __restrict__ bias, float* __restrict__ out) {
    extern __shared__ char smem[];
    float* biasS = (float*)smem;
    const uint32_t sb = smem_u32(smem) + SMEM_BIAS_B;

    const int tid = threadIdx.x, lane = tid & 31, warp = tid >> 5;
    const int wm = warp >> 2, wn = warp & 3;         // 2 x 4 warp grid, 64x64 warp tile
    const int ntile = blockIdx.x, mtile = blockIdx.y;

    biasS[tid] = bias[ntile * NT + tid];             // 256 threads == NT

    const __half* gA = g_xa + (size_t)mtile * MT * K_DIM;
    const __half* gB = g_wh + (size_t)ntile * NT * K_DIM;

    auto load_stage = [&](int slot, int kt) {
        const int k0 = kt * KT;
        const uint32_t sA = sb + slot * STAGE_B;
        const uint32_t sB = sA + A_STAGE_B;
#pragma unroll
        for (int it = 0; it < 2; it++) {             // A: 128 rows * 4 chunks = 512
            int idx = tid + it * 256;
            int r = idx >> 2, c = idx & 3;
            cp_async16(sA + r * AROWB + c * 16, gA + (size_t)r * K_DIM + k0 + c * 8);
        }
#pragma unroll
        for (int it = 0; it < 4; it++) {             // B: 256 rows * 4 chunks = 1024
            int idx = tid + it * 256;
            int r = idx >> 2, c = idx & 3;
            cp_async16(sB + r * AROWB + c * 16, gB + (size_t)r * K_DIM + k0 + c * 8);
        }
        asm volatile("cp.async.commit_group;" ::: "memory");
    };

#pragma unroll
    for (int s = 0; s < STAGES - 1; s++) load_stage(s, s);

    float acc[4][8][4];
#pragma unroll
    for (int i = 0; i < 4; i++)
#pragma unroll
        for (int j = 0; j < 8; j++)
#pragma unroll
            for (int q = 0; q < 4; q++) acc[i][j][q] = 0.0f;

    const int lrow = lane & 15, lch = lane >> 4;     // ldmatrix.x4 lane addressing

    for (int kt = 0; kt < NKT; kt++) {
        const int slot = kt % STAGES;
        asm volatile("cp.async.wait_group %0;" :: "n"(STAGES - 2));
        __syncthreads();

        // Issue next stage first (slot consumed at kt-1; all warps past via sync).
        // Tail commits an EMPTY group so "all but newest 3" always covers stage kt.
        const int nk = kt + STAGES - 1;
        if (nk < NKT) load_stage(nk % STAGES, nk);
        else asm volatile("cp.async.commit_group;" ::: "memory");

        const uint32_t sA = sb + slot * STAGE_B;
        const uint32_t sB = sA + A_STAGE_B;
#pragma unroll
        for (int k16 = 0; k16 < 2; k16++) {
            uint32_t aF[4][4], bF[4][4];
#pragma unroll
            for (int i = 0; i < 4; i++)
                ldsm4(aF[i], sA + (wm * 64 + i * 16 + lrow) * AROWB + (k16 * 2 + lch) * 16);
#pragma unroll
            for (int j = 0; j < 4; j++)
                ldsm4(bF[j], sB + (wn * 64 + j * 16 + lrow) * AROWB + (k16 * 2 + lch) * 16);
#pragma unroll
            for (int i = 0; i < 4; i++)
#pragma unroll
                for (int j = 0; j < 8; j++) {
                    uint32_t b0 = bF[j >> 1][(j & 1) ? 1 : 0];
                    uint32_t b1 = bF[j >> 1][(j & 1) ? 3 : 2];
                    mma16816(acc[i][j], aF[i], b0, b1);
                }
        }
    }

    // -------- epilogue: direct fp32 stores, reference double rounding --------
    // C fragment: c0,c1 -> row (lane>>2), cols 2*(lane&3)+{0,1}; c2,c3 -> row+8.
    const int r0 = lane >> 2, q2 = 2 * (lane & 3);
#pragma unroll
    for (int i = 0; i < 4; i++) {
        size_t m0 = (size_t)mtile * MT + wm * 64 + i * 16 + r0;
#pragma unroll
        for (int j = 0; j < 8; j++) {
            int nl = wn * 64 + j * 8 + q2;
            float b0 = biasS[nl], b1 = biasS[nl + 1];
            auto pack2 = [&](float v0, float v1) {
                float2 o;
                o.x = __bfloat162float(__float2bfloat16_rn(
                          __bfloat162float(__float2bfloat16_rn(v0)) + b0));
                o.y = __bfloat162float(__float2bfloat16_rn(
                          __bfloat162float(__float2bfloat16_rn(v1)) + b1));
                return o;
            };
            size_t col = (size_t)ntile * NT + nl;
            *(float2*)(out + m0 * N_DIM + col)       = pack2(acc[i][j][0], acc[i][j][1]);
            *(float2*)(out + (m0 + 8) * N_DIM + col) = pack2(acc[i][j][2], acc[i][j][3]);
        }
    }
}

// ================= launch =================
extern "C" void kernel_launch(void* const* d_in, const int* in_sizes, int n_in,
                              void* d_out, int out_size) {
    // Resolve inputs BY ELEMENT COUNT (ordering-proof):
    //   x: 134217728, weight: 4194304, bias: 4096.
    const float* x = nullptr;
    const float* w = nullptr;
    const float* bias = nullptr;
    for (int i = 0; i < n_in; i++) {
        if (in_sizes[i] == M_DIM * K_DIM) x = (const float*)d_in[i];
        else if (in_sizes[i] == N_DIM * K_DIM) w = (const float*)d_in[i];
        else if (in_sizes[i] == N_DIM) bias = (const float*)d_in[i];
    }
    float* out = (float*)d_out;   // fp32 output buffer

    cudaFuncSetAttribute(gemm_kernel, cudaFuncAttributeMaxDynamicSharedMemorySize, SMEM_TOTAL);

    conv_x_kernel<<<(int)((size_t)M_DIM * K_DIM / 2048), 256>>>(x);
    conv_w_kernel<<<(int)((size_t)N_DIM * K_DIM / 2048), 256>>>(w);
    gemm_kernel<<<dim3(N_DIM / NT, M_DIM / MT), 256, SMEM_TOTAL>>>(bias, out);
}

// round 13
// speedup vs baseline: 1.0952x; 1.0952x over previous
#include <cuda_runtime.h>
#include <cuda_fp16.h>
#include <cuda_bf16.h>
#include <cstdint>

// ================= problem constants =================
constexpr int K_DIM = 1024;
constexpr int N_DIM = 4096;
constexpr int M_DIM = 32768;

constexpr int MT = 128;               // CTA tile M
constexpr int NT = 128;               // CTA tile N  (shrunk so 2 CTAs fit per SM)
constexpr int KT = 32;                // CTA tile K per stage
constexpr int STAGES = 4;
constexpr int NKT = K_DIM / KT;       // 32 k-iterations

constexpr int AROWB = 80;             // smem row stride: 64B data + 16B pad (conflict-free)
constexpr int A_STAGE_B = MT * AROWB; // 10240
constexpr int B_STAGE_B = NT * AROWB; // 10240
constexpr int STAGE_B = A_STAGE_B + B_STAGE_B;       // 20480
constexpr int SMEM_BIAS_B = 512;
constexpr int SMEM_TOTAL = SMEM_BIAS_B + STAGES * STAGE_B;  // 82432  (x2 CTAs = 165KB <= 228KB)

// ============ device scratch (__device__ globals; no allocs allowed) ============
__device__ __align__(128) __half g_xa[(size_t)M_DIM * K_DIM];  // BF15(x) as fp16, [M][K]
__device__ __align__(128) __half g_wh[(size_t)N_DIM * K_DIM];  // fp16(W), [N][K]

// ================= helpers =================
__device__ __forceinline__ uint32_t smem_u32(const void* p) {
    uint32_t a;
    asm("{ .reg .u64 t; cvta.to.shared.u64 t, %1; cvt.u32.u64 %0, t; }" : "=r"(a) : "l"(p));
    return a;
}
__device__ __forceinline__ void cp_async16(uint32_t s, const void* g) {
    asm volatile("cp.async.cg.shared.global [%0], [%1], 16;" :: "r"(s), "l"(g));
}
__device__ __forceinline__ void ldsm4(uint32_t* r, uint32_t addr) {
    asm volatile("ldmatrix.sync.aligned.m8n8.x4.shared.b16 {%0,%1,%2,%3}, [%4];"
                 : "=r"(r[0]), "=r"(r[1]), "=r"(r[2]), "=r"(r[3]) : "r"(addr));
}
__device__ __forceinline__ void mma16816(float* c, const uint32_t* a, uint32_t b0, uint32_t b1) {
    asm volatile(
        "mma.sync.aligned.m16n8k16.row.col.f32.f16.f16.f32 "
        "{%0,%1,%2,%3},{%4,%5,%6,%7},{%8,%9},{%0,%1,%2,%3};"
        : "+f"(c[0]), "+f"(c[1]), "+f"(c[2]), "+f"(c[3])
        : "r"(a[0]), "r"(a[1]), "r"(a[2]), "r"(a[3]), "r"(b0), "r"(b1));
}

// ================= conversion kernels (measured ~78% HBM — done) =================
__global__ void conv_x_kernel(const float* __restrict__ x) {
    size_t i = ((size_t)blockIdx.x * blockDim.x + threadIdx.x) * 8;
    float4 f0 = *(const float4*)(x + i);
    float4 f1 = *(const float4*)(x + i + 4);
    auto bf15 = [](float v) { return __uint_as_float(__float_as_uint(v) & 0xFFFE0000u); };
    __half2 h[4];
    h[0] = __floats2half2_rn(bf15(f0.x), bf15(f0.y));
    h[1] = __floats2half2_rn(bf15(f0.z), bf15(f0.w));
    h[2] = __floats2half2_rn(bf15(f1.x), bf15(f1.y));
    h[3] = __floats2half2_rn(bf15(f1.z), bf15(f1.w));
    *(uint4*)(g_xa + i) = *(uint4*)h;
}

__global__ void conv_w_kernel(const float* __restrict__ w) {
    size_t i = ((size_t)blockIdx.x * blockDim.x + threadIdx.x) * 8;
    float4 f0 = *(const float4*)(w + i);
    float4 f1 = *(const float4*)(w + i + 4);
    __half2 h[4];
    h[0] = __floats2half2_rn(f0.x, f0.y);
    h[1] = __floats2half2_rn(f0.z, f0.w);
    h[2] = __floats2half2_rn(f1.x, f1.y);
    h[3] = __floats2half2_rn(f1.z, f1.w);
    *(uint4*)(g_wh + i) = *(uint4*)h;
}

// ============ GEMM kernel: occupancy-2, 128x128 CTA, 64x32 warp tile ============
__global__ __launch_bounds__(256, 2)
void gemm_kernel(const float* __restrict__ bias, float* __restrict__ out) {
    extern __shared__ char smem[];
    float* biasS = (float*)smem;
    const uint32_t sb = smem_u32(smem) + SMEM_BIAS_B;

    const int tid = threadIdx.x, lane = tid & 31, warp = tid >> 5;
    const int wm = warp >> 2, wn = warp & 3;         // 2 x 4 warp grid, 64x32 warp tile
    const int ntile = blockIdx.x, mtile = blockIdx.y;

    if (tid < NT) biasS[tid] = bias[ntile * NT + tid];

    const __half* gA = g_xa + (size_t)mtile * MT * K_DIM;
    const __half* gB = g_wh + (size_t)ntile * NT * K_DIM;

    auto load_stage = [&](int slot, int kt) {
        const int k0 = kt * KT;
        const uint32_t sA = sb + slot * STAGE_B;
        const uint32_t sB = sA + A_STAGE_B;
#pragma unroll
        for (int it = 0; it < 2; it++) {             // A: 128 rows * 4 chunks = 512
            int idx = tid + it * 256;
            int r = idx >> 2, c = idx & 3;
            cp_async16(sA + r * AROWB + c * 16, gA + (size_t)r * K_DIM + k0 + c * 8);
        }
#pragma unroll
        for (int it = 0; it < 2; it++) {             // B: 128 rows * 4 chunks = 512
            int idx = tid + it * 256;
            int r = idx >> 2, c = idx & 3;
            cp_async16(sB + r * AROWB + c * 16, gB + (size_t)r * K_DIM + k0 + c * 8);
        }
        asm volatile("cp.async.commit_group;" ::: "memory");
    };

#pragma unroll
    for (int s = 0; s < STAGES - 1; s++) load_stage(s, s);

    float acc[4][4][4];                               // 64 fp32 accum regs/thread
#pragma unroll
    for (int i = 0; i < 4; i++)
#pragma unroll
        for (int j = 0; j < 4; j++)
#pragma unroll
            for (int q = 0; q < 4; q++) acc[i][j][q] = 0.0f;

    const int lrow = lane & 15, lch = lane >> 4;     // ldmatrix.x4 lane addressing

    for (int kt = 0; kt < NKT; kt++) {
        const int slot = kt % STAGES;
        asm volatile("cp.async.wait_group %0;" :: "n"(STAGES - 2));
        __syncthreads();

        // Issue next stage first (its slot was consumed at kt-1; all warps past
        // via the sync above). Tail commits an EMPTY group so "all but newest
        // STAGES-2" always covers stage kt.
        const int nk = kt + STAGES - 1;
        if (nk < NKT) load_stage(nk % STAGES, nk);
        else asm volatile("cp.async.commit_group;" ::: "memory");

        const uint32_t sA = sb + slot * STAGE_B;
        const uint32_t sB = sA + A_STAGE_B;
#pragma unroll
        for (int k16 = 0; k16 < 2; k16++) {
            uint32_t aF[4][4], bF[2][4];
#pragma unroll
            for (int i = 0; i < 4; i++)
                ldsm4(aF[i], sA + (wm * 64 + i * 16 + lrow) * AROWB + (k16 * 2 + lch) * 16);
#pragma unroll
            for (int j = 0; j < 2; j++)
                ldsm4(bF[j], sB + (wn * 32 + j * 16 + lrow) * AROWB + (k16 * 2 + lch) * 16);
#pragma unroll
            for (int i = 0; i < 4; i++)
#pragma unroll
                for (int j = 0; j < 4; j++) {        // 4 n8-groups across 32 cols
                    uint32_t b0 = bF[j >> 1][(j & 1) ? 1 : 0];
                    uint32_t b1 = bF[j >> 1][(j & 1) ? 3 : 2];
                    mma16816(acc[i][j], aF[i], b0, b1);
                }
        }
    }

    // -------- epilogue: direct fp32 stores, reference double rounding --------
    // C fragment: c0,c1 -> row (lane>>2), cols 2*(lane&3)+{0,1}; c2,c3 -> row+8.
    const int r0 = lane >> 2, q2 = 2 * (lane & 3);
#pragma unroll
    for (int i = 0; i < 4; i++) {
        size_t m0 = (size_t)mtile * MT + wm * 64 + i * 16 + r0;
#pragma unroll
        for (int j = 0; j < 4; j++) {
            int nl = wn * 32 + j * 8 + q2;
            float b0 = biasS[nl], b1 = biasS[nl + 1];
            auto pack2 = [&](float v0, float v1) {
                float2 o;
                o.x = __bfloat162float(__float2bfloat16_rn(
                          __bfloat162float(__float2bfloat16_rn(v0)) + b0));
                o.y = __bfloat162float(__float2bfloat16_rn(
                          __bfloat162float(__float2bfloat16_rn(v1)) + b1));
                return o;
            };
            size_t col = (size_t)ntile * NT + nl;
            *(float2*)(out + m0 * N_DIM + col)       = pack2(acc[i][j][0], acc[i][j][1]);
            *(float2*)(out + (m0 + 8) * N_DIM + col) = pack2(acc[i][j][2], acc[i][j][3]);
        }
    }
}

// ================= launch =================
extern "C" void kernel_launch(void* const* d_in, const int* in_sizes, int n_in,
                              void* d_out, int out_size) {
    // Resolve inputs BY ELEMENT COUNT (ordering-proof):
    //   x: 134217728, weight: 4194304, bias: 4096.
    const float* x = nullptr;
    const float* w = nullptr;
    const float* bias = nullptr;
    for (int i = 0; i < n_in; i++) {
        if (in_sizes[i] == M_DIM * K_DIM) x = (const float*)d_in[i];
        else if (in_sizes[i] == N_DIM * K_DIM) w = (const float*)d_in[i];
        else if (in_sizes[i] == N_DIM) bias = (const float*)d_in[i];
    }
    float* out = (float*)d_out;   // fp32 output buffer

    cudaFuncSetAttribute(gemm_kernel, cudaFuncAttributeMaxDynamicSharedMemorySize, SMEM_TOTAL);

    conv_x_kernel<<<(int)((size_t)M_DIM * K_DIM / 2048), 256>>>(x);
    conv_w_kernel<<<(int)((size_t)N_DIM * K_DIM / 2048), 256>>>(w);
    gemm_kernel<<<dim3(N_DIM / NT, M_DIM / MT), 256, SMEM_TOTAL>>>(bias, out);
}

// round 15
// speedup vs baseline: 1.2137x; 1.1082x over previous
#include <cuda_runtime.h>
#include <cuda_fp16.h>
#include <cuda_bf16.h>
#include <cstdint>

// ================= problem constants =================
constexpr int K_DIM = 1024;
constexpr int N_DIM = 4096;
constexpr int M_DIM = 32768;

constexpr int MT = 128;               // CTA tile M
constexpr int NT = 128;               // CTA tile N
constexpr int KT = 64;                // CTA tile K per super-stage
constexpr int STAGES = 3;
constexpr int NKT = K_DIM / KT;       // 16 k-iterations

constexpr int AROWB = 144;            // 128B data + 16B pad; ldsm rows hit distinct banks (36r mod 32)
constexpr int A_STAGE_B = MT * AROWB; // 18432
constexpr int B_STAGE_B = NT * AROWB; // 18432
constexpr int STAGE_B = A_STAGE_B + B_STAGE_B;       // 36864
constexpr int SMEM_BIAS_B = 512;
constexpr int SMEM_TOTAL = SMEM_BIAS_B + STAGES * STAGE_B;  // 111104 (x2 CTAs = 222KB <= 228KB)

// ============ device scratch (__device__ globals; no allocs allowed) ============
__device__ __align__(128) __half g_xa[(size_t)M_DIM * K_DIM];  // BF15(x) as fp16, [M][K]
__device__ __align__(128) __half g_wh[(size_t)N_DIM * K_DIM];  // fp16(W), [N][K]

// ================= helpers =================
__device__ __forceinline__ uint32_t smem_u32(const void* p) {
    uint32_t a;
    asm("{ .reg .u64 t; cvta.to.shared.u64 t, %1; cvt.u32.u64 %0, t; }" : "=r"(a) : "l"(p));
    return a;
}
__device__ __forceinline__ void cp_async16(uint32_t s, const void* g) {
    asm volatile("cp.async.cg.shared.global [%0], [%1], 16;" :: "r"(s), "l"(g));
}
__device__ __forceinline__ void ldsm4(uint32_t* r, uint32_t addr) {
    asm volatile("ldmatrix.sync.aligned.m8n8.x4.shared.b16 {%0,%1,%2,%3}, [%4];"
                 : "=r"(r[0]), "=r"(r[1]), "=r"(r[2]), "=r"(r[3]) : "r"(addr));
}
__device__ __forceinline__ void mma16816(float* c, const uint32_t* a, uint32_t b0, uint32_t b1) {
    asm volatile(
        "mma.sync.aligned.m16n8k16.row.col.f32.f16.f16.f32 "
        "{%0,%1,%2,%3},{%4,%5,%6,%7},{%8,%9},{%0,%1,%2,%3};"
        : "+f"(c[0]), "+f"(c[1]), "+f"(c[2]), "+f"(c[3])
        : "r"(a[0]), "r"(a[1]), "r"(a[2]), "r"(a[3]), "r"(b0), "r"(b1));
}

// ================= conversion kernels (measured ~78% HBM — done) =================
__global__ void conv_x_kernel(const float* __restrict__ x) {
    size_t i = ((size_t)blockIdx.x * blockDim.x + threadIdx.x) * 8;
    float4 f0 = *(const float4*)(x + i);
    float4 f1 = *(const float4*)(x + i + 4);
    auto bf15 = [](float v) { return __uint_as_float(__float_as_uint(v) & 0xFFFE0000u); };
    __half2 h[4];
    h[0] = __floats2half2_rn(bf15(f0.x), bf15(f0.y));
    h[1] = __floats2half2_rn(bf15(f0.z), bf15(f0.w));
    h[2] = __floats2half2_rn(bf15(f1.x), bf15(f1.y));
    h[3] = __floats2half2_rn(bf15(f1.z), bf15(f1.w));
    *(uint4*)(g_xa + i) = *(uint4*)h;
}

__global__ void conv_w_kernel(const float* __restrict__ w) {
    size_t i = ((size_t)blockIdx.x * blockDim.x + threadIdx.x) * 8;
    float4 f0 = *(const float4*)(w + i);
    float4 f1 = *(const float4*)(w + i + 4);
    __half2 h[4];
    h[0] = __floats2half2_rn(f0.x, f0.y);
    h[1] = __floats2half2_rn(f0.z, f0.w);
    h[2] = __floats2half2_rn(f1.x, f1.y);
    h[3] = __floats2half2_rn(f1.z, f1.w);
    *(uint4*)(g_wh + i) = *(uint4*)h;
}

// ======== GEMM: occ-2, 128x128 CTA, 64x32 warp tile, KT=64 super-stages x3 ========
__global__ __launch_bounds__(256, 2)
void gemm_kernel(const float* __restrict__ bias, float* __restrict__ out) {
    extern __shared__ char smem[];
    float* biasS = (float*)smem;
    const uint32_t sb = smem_u32(smem) + SMEM_BIAS_B;

    const int tid = threadIdx.x, lane = tid & 31, warp = tid >> 5;
    const int wm = warp >> 2, wn = warp & 3;         // 2 x 4 warp grid, 64x32 warp tile
    const int ntile = blockIdx.x, mtile = blockIdx.y;

    if (tid < NT) biasS[tid] = bias[ntile * NT + tid];

    const __half* gA = g_xa + (size_t)mtile * MT * K_DIM;
    const __half* gB = g_wh + (size_t)ntile * NT * K_DIM;

    // KT=64: each row is 128B data = 8 x 16B chunks; 128 rows for A and B.
    auto load_stage = [&](int slot, int kt) {
        const int k0 = kt * KT;
        const uint32_t sA = sb + slot * STAGE_B;
        const uint32_t sB = sA + A_STAGE_B;
#pragma unroll
        for (int it = 0; it < 4; it++) {             // A: 128 rows * 8 chunks = 1024
            int idx = tid + it * 256;
            int r = idx >> 3, c = idx & 7;
            cp_async16(sA + r * AROWB + c * 16, gA + (size_t)r * K_DIM + k0 + c * 8);
        }
#pragma unroll
        for (int it = 0; it < 4; it++) {             // B: 128 rows * 8 chunks = 1024
            int idx = tid + it * 256;
            int r = idx >> 3, c = idx & 7;
            cp_async16(sB + r * AROWB + c * 16, gB + (size_t)r * K_DIM + k0 + c * 8);
        }
        asm volatile("cp.async.commit_group;" ::: "memory");
    };

#pragma unroll
    for (int s = 0; s < STAGES - 1; s++) load_stage(s, s);

    float acc[4][4][4];                               // 64 fp32 accum regs/thread
#pragma unroll
    for (int i = 0; i < 4; i++)
#pragma unroll
        for (int j = 0; j < 4; j++)
#pragma unroll
            for (int q = 0; q < 4; q++) acc[i][j][q] = 0.0f;

    const int lrow = lane & 15, lch = lane >> 4;     // ldmatrix.x4 lane addressing

    for (int kt = 0; kt < NKT; kt++) {
        const int slot = kt % STAGES;
        asm volatile("cp.async.wait_group %0;" :: "n"(STAGES - 2));
        __syncthreads();

        // Issue next super-stage first (slot consumed at kt-1; all warps past via
        // the sync). Tail commits an EMPTY group so "all but newest STAGES-2"
        // always covers stage kt.
        const int nk = kt + STAGES - 1;
        if (nk < NKT) load_stage(nk % STAGES, nk);
        else asm volatile("cp.async.commit_group;" ::: "memory");

        const uint32_t sA = sb + slot * STAGE_B;
        const uint32_t sB = sA + A_STAGE_B;
#pragma unroll
        for (int k16 = 0; k16 < 4; k16++) {          // 4 x k16 per KT=64 super-stage
            uint32_t aF[4][4], bF[2][4];
#pragma unroll
            for (int i = 0; i < 4; i++)
                ldsm4(aF[i], sA + (wm * 64 + i * 16 + lrow) * AROWB + (k16 * 2 + lch) * 16);
#pragma unroll
            for (int j = 0; j < 2; j++)
                ldsm4(bF[j], sB + (wn * 32 + j * 16 + lrow) * AROWB + (k16 * 2 + lch) * 16);
#pragma unroll
            for (int i = 0; i < 4; i++)
#pragma unroll
                for (int j = 0; j < 4; j++) {        // 4 n8-groups across 32 cols
                    uint32_t b0 = bF[j >> 1][(j & 1) ? 1 : 0];
                    uint32_t b1 = bF[j >> 1][(j & 1) ? 3 : 2];
                    mma16816(acc[i][j], aF[i], b0, b1);
                }
        }
    }

    // -------- epilogue: direct fp32 stores, reference double rounding --------
    // C fragment: c0,c1 -> row (lane>>2), cols 2*(lane&3)+{0,1}; c2,c3 -> row+8.
    const int r0 = lane >> 2, q2 = 2 * (lane & 3);
#pragma unroll
    for (int i = 0; i < 4; i++) {
        size_t m0 = (size_t)mtile * MT + wm * 64 + i * 16 + r0;
#pragma unroll
        for (int j = 0; j < 4; j++) {
            int nl = wn * 32 + j * 8 + q2;
            float b0 = biasS[nl], b1 = biasS[nl + 1];
            auto pack2 = [&](float v0, float v1) {
                float2 o;
                o.x = __bfloat162float(__float2bfloat16_rn(
                          __bfloat162float(__float2bfloat16_rn(v0)) + b0));
                o.y = __bfloat162float(__float2bfloat16_rn(
                          __bfloat162float(__float2bfloat16_rn(v1)) + b1));
                return o;
            };
            size_t col = (size_t)ntile * NT + nl;
            *(float2*)(out + m0 * N_DIM + col)       = pack2(acc[i][j][0], acc[i][j][1]);
            *(float2*)(out + (m0 + 8) * N_DIM + col) = pack2(acc[i][j][2], acc[i][j][3]);
        }
    }
}

// ================= launch =================
extern "C" void kernel_launch(void* const* d_in, const int* in_sizes, int n_in,
                              void* d_out, int out_size) {
    // Resolve inputs BY ELEMENT COUNT (ordering-proof):
    //   x: 134217728, weight: 4194304, bias: 4096.
    const float* x = nullptr;
    const float* w = nullptr;
    const float* bias = nullptr;
    for (int i = 0; i < n_in; i++) {
        if (in_sizes[i] == M_DIM * K_DIM) x = (const float*)d_in[i];
        else if (in_sizes[i] == N_DIM * K_DIM) w = (const float*)d_in[i];
        else if (in_sizes[i] == N_DIM) bias = (const float*)d_in[i];
    }
    float* out = (float*)d_out;   // fp32 output buffer

    cudaFuncSetAttribute(gemm_kernel, cudaFuncAttributeMaxDynamicSharedMemorySize, SMEM_TOTAL);

    conv_x_kernel<<<(int)((size_t)M_DIM * K_DIM / 2048), 256>>>(x);
    conv_w_kernel<<<(int)((size_t)N_DIM * K_DIM / 2048), 256>>>(w);
    gemm_kernel<<<dim3(N_DIM / NT, M_DIM / MT), 256, SMEM_TOTAL>>>(bias, out);
}